// round 1
// baseline (speedup 1.0000x reference)
#include <cuda_runtime.h>

#define NS   1024
#define NB   16
#define NQ   8192
#define NDV  64

#define THREADS 128
#define QPT     2
#define QB      (THREADS * QPT)   // 256 queries per block

__global__ __launch_bounds__(THREADS)
void nn_argmin_gather_kernel(
    const float* __restrict__ sample_vals,   // [NS, NB, NDV]
    const float* __restrict__ sample_posns,  // [NS, NB, 2]
    const float* __restrict__ query_posns,   // [NQ, NB, 2]
    float* __restrict__ out)                 // [NQ, NB, NDV]
{
    __shared__ float4 samp[NS];      // (-2*sx, -2*sy, s2, pad)
    __shared__ int    bidx_sh[QB];

    const int tid   = threadIdx.x;
    const int b     = blockIdx.y;
    const int qbase = blockIdx.x * QB;

    // Stage this batch's samples into shared memory.
    // s2 mimics reference rounding: mul, mul, add (no fma).
    // Folding -2 into coords is bit-exact (scale by power of two).
    for (int s = tid; s < NS; s += THREADS) {
        const float2 p = *reinterpret_cast<const float2*>(sample_posns + (s * NB + b) * 2);
        const float s2 = __fadd_rn(__fmul_rn(p.x, p.x), __fmul_rn(p.y, p.y));
        samp[s] = make_float4(-2.0f * p.x, -2.0f * p.y, s2, 0.0f);
    }
    __syncthreads();

    float qx[QPT], qy[QPT], q2[QPT], best[QPT];
    int   bi[QPT];

#pragma unroll
    for (int j = 0; j < QPT; j++) {
        const int q = qbase + tid + j * THREADS;
        const float2 p = *reinterpret_cast<const float2*>(query_posns + (q * NB + b) * 2);
        qx[j] = p.x;
        qy[j] = p.y;
        q2[j] = __fadd_rn(__fmul_rn(p.x, p.x), __fmul_rn(p.y, p.y));
        best[j] = __int_as_float(0x7f800000);  // +inf
        bi[j]   = 0;
    }

    // Brute-force argmin over all 1024 samples.
    // d = (q2 - 2*qs) + s2, with qs = fma(qy, sy, qx*sx), replicated exactly:
    //   t  = fma(qy, -2sy, qx * (-2sx))  ==  -2 * fma(qy, sy, qx*sx)   (bit-exact)
    //   d  = (q2 + t) + s2
#pragma unroll 8
    for (int s = 0; s < NS; s++) {
        const float4 v = samp[s];
#pragma unroll
        for (int j = 0; j < QPT; j++) {
            const float t = __fmaf_rn(qy[j], v.y, __fmul_rn(qx[j], v.x));
            const float d = __fadd_rn(__fadd_rn(q2[j], t), v.z);
            if (d < best[j]) { best[j] = d; bi[j] = s; }   // strict < => first-index tie-break
        }
    }

#pragma unroll
    for (int j = 0; j < QPT; j++) bidx_sh[tid + j * THREADS] = bi[j];
    __syncthreads();

    // Cooperative, coalesced gather of winning value rows (16 float4 per query).
    const float4* __restrict__ sv4  = reinterpret_cast<const float4*>(sample_vals);
    float4* __restrict__       out4 = reinterpret_cast<float4*>(out);
    const int V4 = NDV / 4;  // 16

    for (int item = tid; item < QB * V4; item += THREADS) {
        const int j = item >> 4;        // query within block
        const int v = item & (V4 - 1);  // float4 chunk within row
        const int s = bidx_sh[j];
        const int q = qbase + j;
        out4[(q * NB + b) * V4 + v] = sv4[(s * NB + b) * V4 + v];
    }
}

extern "C" void kernel_launch(void* const* d_in, const int* in_sizes, int n_in,
                              void* d_out, int out_size)
{
    const float* sample_vals  = (const float*)d_in[0];  // [1024, 16, 64]
    const float* sample_posns = (const float*)d_in[1];  // [1024, 16, 2]
    const float* query_posns  = (const float*)d_in[2];  // [8192, 16, 2]
    float* out = (float*)d_out;                          // [8192, 16, 64]

    dim3 grid(NQ / QB, NB);   // (32, 16)
    dim3 block(THREADS);
    nn_argmin_gather_kernel<<<grid, block>>>(sample_vals, sample_posns, query_posns, out);
}

// round 2
// speedup vs baseline: 1.0824x; 1.0824x over previous
#include <cuda_runtime.h>

#define NS   1024
#define NB   16
#define NQ   8192
#define NDV  64

#define THREADS 128
#define QPT     2
#define QB      (THREADS * QPT)   // 256 queries per block

typedef unsigned long long u64;

// ---- packed f32x2 helpers (sm_103a). Per-lane IEEE round-to-nearest:
// bit-exact vs the scalar sequence the reference uses. ----
__device__ __forceinline__ u64 pk2(float lo, float hi) {
    u64 r; asm("mov.b64 %0, {%1,%2};" : "=l"(r) : "f"(lo), "f"(hi)); return r;
}
__device__ __forceinline__ void upk2(u64 v, float& lo, float& hi) {
    asm("mov.b64 {%0,%1}, %2;" : "=f"(lo), "=f"(hi) : "l"(v));
}
__device__ __forceinline__ u64 mul2(u64 a, u64 b) {
    u64 r; asm("mul.rn.f32x2 %0, %1, %2;" : "=l"(r) : "l"(a), "l"(b)); return r;
}
__device__ __forceinline__ u64 fma2(u64 a, u64 b, u64 c) {
    u64 r; asm("fma.rn.f32x2 %0, %1, %2, %3;" : "=l"(r) : "l"(a), "l"(b), "l"(c)); return r;
}
__device__ __forceinline__ u64 add2(u64 a, u64 b) {
    u64 r; asm("add.rn.f32x2 %0, %1, %2;" : "=l"(r) : "l"(a), "l"(b)); return r;
}

__global__ __launch_bounds__(THREADS)
void nn_argmin_gather_kernel(
    const float* __restrict__ sample_vals,   // [NS, NB, NDV]
    const float* __restrict__ sample_posns,  // [NS, NB, 2]
    const float* __restrict__ query_posns,   // [NQ, NB, 2]
    float* __restrict__ out)                 // [NQ, NB, NDV]
{
    __shared__ float4 sX[NS / 4];   // -2*sx, 4 samples per entry
    __shared__ float4 sY[NS / 4];   // -2*sy
    __shared__ float4 sZ[NS / 4];   // s2 (mul,mul,add — reference rounding)
    __shared__ int    bidx_sh[QB];

    const int tid   = threadIdx.x;
    const int b     = blockIdx.y;
    const int qbase = blockIdx.x * QB;

    // Stage samples as SoA float4 groups of 4.
    for (int i = tid; i < NS / 4; i += THREADS) {
        float4 X, Y, Z;
#pragma unroll
        for (int u = 0; u < 4; u++) {
            const int s = 4 * i + u;
            const float2 p = *reinterpret_cast<const float2*>(sample_posns + (s * NB + b) * 2);
            reinterpret_cast<float*>(&X)[u] = -2.0f * p.x;   // power-of-2 scale: bit-exact fold
            reinterpret_cast<float*>(&Y)[u] = -2.0f * p.y;
            reinterpret_cast<float*>(&Z)[u] = __fadd_rn(__fmul_rn(p.x, p.x), __fmul_rn(p.y, p.y));
        }
        sX[i] = X; sY[i] = Y; sZ[i] = Z;
    }
    __syncthreads();

    u64 qx2[QPT], qy2[QPT], q22[QPT];
    float best[QPT];
    int   bi[QPT];

#pragma unroll
    for (int j = 0; j < QPT; j++) {
        const int q = qbase + tid + j * THREADS;
        const float2 p = *reinterpret_cast<const float2*>(query_posns + (q * NB + b) * 2);
        const float q2 = __fadd_rn(__fmul_rn(p.x, p.x), __fmul_rn(p.y, p.y));
        qx2[j] = pk2(p.x, p.x);
        qy2[j] = pk2(p.y, p.y);
        q22[j] = pk2(q2, q2);
        best[j] = __int_as_float(0x7f800000);  // +inf
        bi[j]   = 0;
    }

    // Argmin over 1024 samples, 4 at a time.
    // Exact reference rounding per element:
    //   t = fma(qy, -2sy, qx*(-2sx))  ( == -2*fma(qy,sy,qx*sx), bit-exact )
    //   d = (q2 + t) + s2
    // FMNMX tournament; index resolved only on (rare) improvement.
#pragma unroll 4
    for (int i = 0; i < NS / 4; i++) {
        const float4 X = sX[i], Y = sY[i], Z = sZ[i];
        const u64 x01 = pk2(X.x, X.y), x23 = pk2(X.z, X.w);
        const u64 y01 = pk2(Y.x, Y.y), y23 = pk2(Y.z, Y.w);
        const u64 z01 = pk2(Z.x, Z.y), z23 = pk2(Z.z, Z.w);
#pragma unroll
        for (int j = 0; j < QPT; j++) {
            const u64 t01 = fma2(qy2[j], y01, mul2(qx2[j], x01));
            const u64 t23 = fma2(qy2[j], y23, mul2(qx2[j], x23));
            const u64 d01 = add2(add2(q22[j], t01), z01);
            const u64 d23 = add2(add2(q22[j], t23), z23);
            float d0, d1, d2, d3;
            upk2(d01, d0, d1);
            upk2(d23, d2, d3);
            const float m = fminf(fminf(d0, d1), fminf(d2, d3));
            if (m < best[j]) {                 // strict < : earlier group wins ties
                best[j] = m;
                const int base = 4 * i;        // find-first-equal: earliest index wins ties
                bi[j] = (d0 == m) ? base
                      : (d1 == m) ? base + 1
                      : (d2 == m) ? base + 2
                                  : base + 3;
            }
        }
    }

#pragma unroll
    for (int j = 0; j < QPT; j++) bidx_sh[tid + j * THREADS] = bi[j];
    __syncthreads();

    // Cooperative, coalesced gather of winning value rows (16 float4 per query).
    const float4* __restrict__ sv4  = reinterpret_cast<const float4*>(sample_vals);
    float4* __restrict__       out4 = reinterpret_cast<float4*>(out);
    const int V4 = NDV / 4;  // 16

    for (int item = tid; item < QB * V4; item += THREADS) {
        const int j = item >> 4;
        const int v = item & (V4 - 1);
        const int s = bidx_sh[j];
        const int q = qbase + j;
        out4[(q * NB + b) * V4 + v] = sv4[(s * NB + b) * V4 + v];
    }
}

extern "C" void kernel_launch(void* const* d_in, const int* in_sizes, int n_in,
                              void* d_out, int out_size)
{
    const float* sample_vals  = (const float*)d_in[0];  // [1024, 16, 64]
    const float* sample_posns = (const float*)d_in[1];  // [1024, 16, 2]
    const float* query_posns  = (const float*)d_in[2];  // [8192, 16, 2]
    float* out = (float*)d_out;                          // [8192, 16, 64]

    dim3 grid(NQ / QB, NB);   // (32, 16)
    dim3 block(THREADS);
    nn_argmin_gather_kernel<<<grid, block>>>(sample_vals, sample_posns, query_posns, out);
}

// round 3
// speedup vs baseline: 1.9330x; 1.7859x over previous
#include <cuda_runtime.h>

#define NS   1024
#define NB   16
#define NQ   8192
#define NDV  64
#define G    16
#define NC   (G * G)

#define QK_THREADS 128

// Scratch (allocation-free rule: __device__ globals)
__device__ float4 g_sorted[NB][NS];          // (-2sx, -2sy, s2, idx-bits), cell-sorted
__device__ int    g_cellStart[NB][NC + 1];

// ---------------------------------------------------------------------------
// Kernel A: bin samples into a GxG grid, one block per batch.
// ---------------------------------------------------------------------------
__global__ __launch_bounds__(256)
void bin_samples_kernel(const float* __restrict__ sample_posns)  // [NS, NB, 2]
{
    __shared__ int s_cnt[NC];
    __shared__ int s_scan[NC];
    __shared__ int s_cur[NC];

    const int tid = threadIdx.x;
    const int b   = blockIdx.x;

    s_cnt[tid] = 0;
    __syncthreads();

    float2 p[4];
    int    cell[4];
#pragma unroll
    for (int k = 0; k < 4; k++) {
        const int s = tid + k * 256;
        p[k] = *reinterpret_cast<const float2*>(sample_posns + (s * NB + b) * 2);
        int cx = (int)(p[k].x * G); cx = cx < 0 ? 0 : (cx > G - 1 ? G - 1 : cx);
        int cy = (int)(p[k].y * G); cy = cy < 0 ? 0 : (cy > G - 1 ? G - 1 : cy);
        cell[k] = cy * G + cx;
        atomicAdd(&s_cnt[cell[k]], 1);
    }
    __syncthreads();

    // Hillis-Steele inclusive scan over 256 cells
    const int cnt = s_cnt[tid];
    s_scan[tid] = cnt;
    for (int ofs = 1; ofs < NC; ofs <<= 1) {
        __syncthreads();
        const int t = (tid >= ofs) ? s_scan[tid - ofs] : 0;
        __syncthreads();
        s_scan[tid] += t;
    }
    __syncthreads();

    const int excl = s_scan[tid] - cnt;
    s_cur[tid] = excl;
    g_cellStart[b][tid] = excl;
    if (tid == 0) g_cellStart[b][NC] = NS;
    __syncthreads();

#pragma unroll
    for (int k = 0; k < 4; k++) {
        const int s   = tid + k * 256;
        const int pos = atomicAdd(&s_cur[cell[k]], 1);
        // s2 with reference rounding: mul, mul, add. -2 fold is bit-exact (pow2 scale).
        const float s2 = __fadd_rn(__fmul_rn(p[k].x, p[k].x), __fmul_rn(p[k].y, p[k].y));
        g_sorted[b][pos] = make_float4(-2.0f * p[k].x, -2.0f * p[k].y, s2, __int_as_float(s));
    }
}

// ---------------------------------------------------------------------------
// Kernel B: exact 1-NN per query via grid pruning + ring expansion, then gather.
// ---------------------------------------------------------------------------
__device__ __forceinline__ void scan_cell(int b, int c, float qx, float qy, float q2,
                                          float& best, int& bi)
{
    const int s0 = g_cellStart[b][c];
    const int s1 = g_cellStart[b][c + 1];
    for (int k = s0; k < s1; k++) {
        const float4 v = g_sorted[b][k];
        // EXACT reference rounding: t = fma(qy,-2sy, qx*(-2sx)); d = (q2 + t) + s2
        const float t = __fmaf_rn(qy, v.y, __fmul_rn(qx, v.x));
        const float d = __fadd_rn(__fadd_rn(q2, t), v.z);
        const int idx = __float_as_int(v.w);
        if (d < best || (d == best && idx < bi)) { best = d; bi = idx; }
    }
}

__global__ __launch_bounds__(QK_THREADS)
void nn_query_kernel(const float* __restrict__ sample_vals,   // [NS, NB, NDV]
                     const float* __restrict__ query_posns,   // [NQ, NB, 2]
                     float* __restrict__ out)                 // [NQ, NB, NDV]
{
    __shared__ int bidx_sh[QK_THREADS];

    const int tid   = threadIdx.x;
    const int b     = blockIdx.y;
    const int qbase = blockIdx.x * QK_THREADS;
    const int q     = qbase + tid;

    const float2 p = *reinterpret_cast<const float2*>(query_posns + (q * NB + b) * 2);
    const float qx = p.x, qy = p.y;
    const float q2 = __fadd_rn(__fmul_rn(qx, qx), __fmul_rn(qy, qy));

    int cx = (int)(qx * G); cx = cx < 0 ? 0 : (cx > G - 1 ? G - 1 : cx);
    int cy = (int)(qy * G); cy = cy < 0 ? 0 : (cy > G - 1 ? G - 1 : cy);

    float best = __int_as_float(0x7f800000);  // +inf
    int   bi   = NS;

    const float h = 1.0f / G;

    // Initial 3x3 region (r = 1), clipped.
    {
        const int x0 = max(0, cx - 1), x1 = min(G - 1, cx + 1);
        const int y0 = max(0, cy - 1), y1 = min(G - 1, cy + 1);
        for (int yy = y0; yy <= y1; yy++)
            for (int xx = x0; xx <= x1; xx++)
                scan_cell(b, yy * G + xx, qx, qy, q2, best, bi);
    }

    // Ring expansion until the geometric bound certifies the winner.
    int r = 1;
    while (true) {
        float db = 3.4e38f;
        if (cx - r > 0)     db = fminf(db, qx - (float)(cx - r) * h);
        if (cx + r < G - 1) db = fminf(db, (float)(cx + r + 1) * h - qx);
        if (cy - r > 0)     db = fminf(db, qy - (float)(cy - r) * h);
        if (cy + r < G - 1) db = fminf(db, (float)(cy + r + 1) * h - qy);
        if (best < db * db - 1e-5f) break;  // margin > total rounding error (~1e-6)
        if (cx - r <= 0 && cx + r >= G - 1 && cy - r <= 0 && cy + r >= G - 1) break;
        r++;
        const int nx0 = cx - r, nx1 = cx + r, ny0 = cy - r, ny1 = cy + r;
        const int xs = max(0, nx0), xe = min(G - 1, nx1);
        if (ny0 >= 0)
            for (int xx = xs; xx <= xe; xx++) scan_cell(b, ny0 * G + xx, qx, qy, q2, best, bi);
        if (ny1 <= G - 1)
            for (int xx = xs; xx <= xe; xx++) scan_cell(b, ny1 * G + xx, qx, qy, q2, best, bi);
        const int ys = max(0, ny0 + 1), ye = min(G - 1, ny1 - 1);
        if (nx0 >= 0)
            for (int yy = ys; yy <= ye; yy++) scan_cell(b, yy * G + nx0, qx, qy, q2, best, bi);
        if (nx1 <= G - 1)
            for (int yy = ys; yy <= ye; yy++) scan_cell(b, yy * G + nx1, qx, qy, q2, best, bi);
    }

    bidx_sh[tid] = bi;
    __syncthreads();

    // Cooperative, coalesced gather of winning value rows (16 float4 per query).
    const float4* __restrict__ sv4  = reinterpret_cast<const float4*>(sample_vals);
    float4* __restrict__       out4 = reinterpret_cast<float4*>(out);
    const int V4 = NDV / 4;  // 16

    for (int item = tid; item < QK_THREADS * V4; item += QK_THREADS) {
        const int j = item >> 4;
        const int v = item & (V4 - 1);
        const int s = bidx_sh[j];
        out4[((qbase + j) * NB + b) * V4 + v] = sv4[(s * NB + b) * V4 + v];
    }
}

extern "C" void kernel_launch(void* const* d_in, const int* in_sizes, int n_in,
                              void* d_out, int out_size)
{
    const float* sample_vals  = (const float*)d_in[0];  // [1024, 16, 64]
    const float* sample_posns = (const float*)d_in[1];  // [1024, 16, 2]
    const float* query_posns  = (const float*)d_in[2];  // [8192, 16, 2]
    float* out = (float*)d_out;                          // [8192, 16, 64]

    bin_samples_kernel<<<NB, 256>>>(sample_posns);

    dim3 grid(NQ / QK_THREADS, NB);  // (64, 16)
    nn_query_kernel<<<grid, QK_THREADS>>>(sample_vals, query_posns, out);
}

// round 5
// speedup vs baseline: 2.4672x; 1.2763x over previous
#include <cuda_runtime.h>

#define NS   1024
#define NB   16
#define NQ   8192
#define NDV  64
#define G    16
#define NC   (G * G)

#define QB 256   // queries per block (also threads per block in query kernel)

// Scratch (allocation-free rule: __device__ globals)
__device__ float4 g_sorted[NB][NS];          // (-2sx, -2sy, s2, idx-bits), cell-sorted
__device__ int    g_cellStart[NB][NC + 1];

// ---------------------------------------------------------------------------
// Kernel A: bin samples into a GxG grid, one block per batch. Shuffle scan.
// ---------------------------------------------------------------------------
__global__ __launch_bounds__(256)
void bin_samples_kernel(const float* __restrict__ sample_posns)  // [NS, NB, 2]
{
    __shared__ int s_cnt[NC];
    __shared__ int s_warp[8];
    __shared__ int s_cur[NC];

    const int tid  = threadIdx.x;
    const int b    = blockIdx.x;
    const int lane = tid & 31;
    const int wid  = tid >> 5;

    s_cnt[tid] = 0;
    __syncthreads();

    float2 p[4];
    int    cell[4];
#pragma unroll
    for (int k = 0; k < 4; k++) {
        const int s = tid + k * 256;
        p[k] = *reinterpret_cast<const float2*>(sample_posns + (s * NB + b) * 2);
        int cx = (int)(p[k].x * G); cx = cx < 0 ? 0 : (cx > G - 1 ? G - 1 : cx);
        int cy = (int)(p[k].y * G); cy = cy < 0 ? 0 : (cy > G - 1 ? G - 1 : cy);
        cell[k] = cy * G + cx;
        atomicAdd(&s_cnt[cell[k]], 1);
    }
    __syncthreads();

    // Exclusive scan over 256 cells: warp shuffle scan + warp-sum offsets.
    const int cnt = s_cnt[tid];
    int incl = cnt;
#pragma unroll
    for (int ofs = 1; ofs < 32; ofs <<= 1) {
        const int t = __shfl_up_sync(0xffffffffu, incl, ofs);
        if (lane >= ofs) incl += t;
    }
    if (lane == 31) s_warp[wid] = incl;
    __syncthreads();
    if (wid == 0 && lane < 8) {
        int w = s_warp[lane];
#pragma unroll
        for (int ofs = 1; ofs < 8; ofs <<= 1) {
            const int t = __shfl_up_sync(0xffu, w, ofs);
            if (lane >= ofs) w += t;
        }
        s_warp[lane] = w;
    }
    __syncthreads();
    const int excl = incl - cnt + (wid > 0 ? s_warp[wid - 1] : 0);

    s_cur[tid] = excl;
    g_cellStart[b][tid] = excl;
    if (tid == 0) g_cellStart[b][NC] = NS;
    __syncthreads();

#pragma unroll
    for (int k = 0; k < 4; k++) {
        const int s   = tid + k * 256;
        const int pos = atomicAdd(&s_cur[cell[k]], 1);
        // s2 with reference rounding: mul, mul, add. -2 fold is bit-exact (pow2 scale).
        const float s2 = __fadd_rn(__fmul_rn(p[k].x, p[k].x), __fmul_rn(p[k].y, p[k].y));
        g_sorted[b][pos] = make_float4(-2.0f * p[k].x, -2.0f * p[k].y, s2, __int_as_float(s));
    }
}

// ---------------------------------------------------------------------------
// Kernel B: exact 1-NN per query; batch's samples staged in SMEM.
// ---------------------------------------------------------------------------
__device__ __forceinline__ void scan_range(const float4* __restrict__ samp,
                                           int s0, int s1,
                                           float qx, float qy, float q2,
                                           float& best, int& bi)
{
    for (int k = s0; k < s1; k++) {
        const float4 v = samp[k];
        // EXACT reference rounding: t = fma(qy,-2sy, qx*(-2sx)); d = (q2 + t) + s2
        const float t = __fmaf_rn(qy, v.y, __fmul_rn(qx, v.x));
        const float d = __fadd_rn(__fadd_rn(q2, t), v.z);
        const int idx = __float_as_int(v.w);
        if (d < best || (d == best && idx < bi)) { best = d; bi = idx; }
    }
}

__global__ __launch_bounds__(QB)
void nn_query_kernel(const float* __restrict__ sample_vals,   // [NS, NB, NDV]
                     const float* __restrict__ query_posns,   // [NQ, NB, 2]
                     float* __restrict__ out)                 // [NQ, NB, NDV]
{
    __shared__ float4 s_samp[NS];        // 16 KB
    __shared__ int    s_cs[NC + 1];      // 257 ints
    __shared__ int    bidx_sh[QB];

    const int tid   = threadIdx.x;
    const int b     = blockIdx.y;
    const int qbase = blockIdx.x * QB;
    const int q     = qbase + tid;

    // Stage batch data into SMEM (coalesced).
#pragma unroll
    for (int i = tid; i < NS; i += QB) s_samp[i] = g_sorted[b][i];
    if (tid < NC) s_cs[tid] = g_cellStart[b][tid];
    if (tid == 0) s_cs[NC] = NS;         // <-- sentinel (was missing: tid never reaches 256)

    const float2 p = *reinterpret_cast<const float2*>(query_posns + (q * NB + b) * 2);
    const float qx = p.x, qy = p.y;
    const float q2 = __fadd_rn(__fmul_rn(qx, qx), __fmul_rn(qy, qy));

    int cx = (int)(qx * G); cx = cx < 0 ? 0 : (cx > G - 1 ? G - 1 : cx);
    int cy = (int)(qy * G); cy = cy < 0 ? 0 : (cy > G - 1 ? G - 1 : cy);

    __syncthreads();

    float best = __int_as_float(0x7f800000);  // +inf
    int   bi   = NS;

    const float h = 1.0f / G;

    // Initial 3x3 region: 3 row-contiguous ranges (cell-sorted order).
    {
        const int x0 = max(0, cx - 1), x1 = min(G - 1, cx + 1);
        const int y0 = max(0, cy - 1), y1 = min(G - 1, cy + 1);
        for (int yy = y0; yy <= y1; yy++)
            scan_range(s_samp, s_cs[yy * G + x0], s_cs[yy * G + x1 + 1], qx, qy, q2, best, bi);
    }

    // Ring expansion until the geometric bound certifies the winner (rare).
    int r = 1;
    while (true) {
        float db = 3.4e38f;
        if (cx - r > 0)     db = fminf(db, qx - (float)(cx - r) * h);
        if (cx + r < G - 1) db = fminf(db, (float)(cx + r + 1) * h - qx);
        if (cy - r > 0)     db = fminf(db, qy - (float)(cy - r) * h);
        if (cy + r < G - 1) db = fminf(db, (float)(cy + r + 1) * h - qy);
        if (best < db * db - 1e-5f) break;  // margin > total rounding error (~1e-6)
        if (cx - r <= 0 && cx + r >= G - 1 && cy - r <= 0 && cy + r >= G - 1) break;
        r++;
        const int nx0 = cx - r, nx1 = cx + r, ny0 = cy - r, ny1 = cy + r;
        const int xs = max(0, nx0), xe = min(G - 1, nx1);
        if (ny0 >= 0)
            scan_range(s_samp, s_cs[ny0 * G + xs], s_cs[ny0 * G + xe + 1], qx, qy, q2, best, bi);
        if (ny1 <= G - 1)
            scan_range(s_samp, s_cs[ny1 * G + xs], s_cs[ny1 * G + xe + 1], qx, qy, q2, best, bi);
        const int ys = max(0, ny0 + 1), ye = min(G - 1, ny1 - 1);
        if (nx0 >= 0)
            for (int yy = ys; yy <= ye; yy++)
                scan_range(s_samp, s_cs[yy * G + nx0], s_cs[yy * G + nx0 + 1], qx, qy, q2, best, bi);
        if (nx1 <= G - 1)
            for (int yy = ys; yy <= ye; yy++)
                scan_range(s_samp, s_cs[yy * G + nx1], s_cs[yy * G + nx1 + 1], qx, qy, q2, best, bi);
    }

    bidx_sh[tid] = bi;
    __syncthreads();

    // Cooperative, coalesced gather of winning value rows (16 float4 per query).
    const float4* __restrict__ sv4  = reinterpret_cast<const float4*>(sample_vals);
    float4* __restrict__       out4 = reinterpret_cast<float4*>(out);
    const int V4 = NDV / 4;  // 16

#pragma unroll
    for (int item = tid; item < QB * V4; item += QB) {
        const int j = item >> 4;
        const int v = item & (V4 - 1);
        const int s = bidx_sh[j];
        out4[((qbase + j) * NB + b) * V4 + v] = sv4[(s * NB + b) * V4 + v];
    }
}

extern "C" void kernel_launch(void* const* d_in, const int* in_sizes, int n_in,
                              void* d_out, int out_size)
{
    const float* sample_vals  = (const float*)d_in[0];  // [1024, 16, 64]
    const float* sample_posns = (const float*)d_in[1];  // [1024, 16, 2]
    const float* query_posns  = (const float*)d_in[2];  // [8192, 16, 2]
    float* out = (float*)d_out;                          // [8192, 16, 64]

    bin_samples_kernel<<<NB, 256>>>(sample_posns);

    dim3 grid(NQ / QB, NB);  // (32, 16)
    nn_query_kernel<<<grid, QB>>>(sample_vals, query_posns, out);
}